// round 13
// baseline (speedup 1.0000x reference)
#include <cuda_runtime.h>

#define N_ENT_MAX 100000
#define SPARSE_THRESHOLD 5

// Scratch (graph-capturable, no allocs). Zero-initialized at module load;
// the gather kernel self-resets counters so every launch/replay starts clean.
__device__ int g_row_ptr[N_ENT_MAX + 1];
__device__ int g_worklist[N_ENT_MAX];
__device__ int g_count;
__device__ unsigned g_bar;
__device__ int g_done;

__device__ __forceinline__ void store_cs(float4* p, float4 v) {
    asm volatile("st.global.cs.v4.f32 [%0], {%1,%2,%3,%4};"
                 :: "l"(p), "f"(v.x), "f"(v.y), "f"(v.z), "f"(v.w) : "memory");
}

// ---------------------------------------------------------------------------
// Prep (rowptr ONLY): boundary-detect over sorted rows, 8 edges/thread.
// Runs concurrently with the gather kernel's phase 0 via PDL.
// ---------------------------------------------------------------------------
__global__ void __launch_bounds__(256)
prep_kernel(const int* __restrict__ rows,
            int* __restrict__ row_ptr,
            int n_edges, int n_ent)
{
    int t  = blockIdx.x * 256 + threadIdx.x;
    int e0 = t * 8;
    if (e0 > n_edges) return;

    int r[9];
    r[0] = (e0 > 0) ? rows[e0 - 1] : -1;
    if (e0 + 8 <= n_edges) {
        int4 v0 = *(const int4*)(rows + e0);
        int4 v1 = *(const int4*)(rows + e0 + 4);
        r[1] = v0.x; r[2] = v0.y; r[3] = v0.z; r[4] = v0.w;
        r[5] = v1.x; r[6] = v1.y; r[7] = v1.z; r[8] = v1.w;
    } else {
        #pragma unroll
        for (int k = 0; k < 8; k++)
            r[k + 1] = (e0 + k < n_edges) ? rows[e0 + k] : n_ent;
    }
    #pragma unroll
    for (int k = 0; k < 8; k++) {
        int e = e0 + k;
        if (e > n_edges) break;
        for (int node = r[k] + 1; node <= r[k + 1]; node++)
            row_ptr[node] = e;
    }
}

// ---------------------------------------------------------------------------
// Gather (persistent one wave = 148*6 blocks, launched with PDL):
//  Phase 0 : classify nodes -> worklist (warp-aggregated atomics) AND
//            zero-fill masked rows. Uniform store-bound work; overlaps prep.
//  Sync    : cudaGridDependencySynchronize() -> prep's row_ptr visible.
//  Barrier : one-wave grid barrier -> worklist globally visible.
//  Phase 1 : one warp per active node; proven unroll-8 512B row gathers.
//  Tail    : last-done block resets counters (deadlock-safe: every block has
//            passed the barrier before any can reach the tail).
// ---------------------------------------------------------------------------
__global__ void __launch_bounds__(256, 6)
gather_kernel(const float4* __restrict__ embeds,
              const int* __restrict__ degrees,
              const int* __restrict__ row_ptr,
              const int* __restrict__ cols,
              int* __restrict__ worklist,
              float4* __restrict__ out,
              int n_ent)
{
    const int tid  = threadIdx.x;
    const int lane = tid & 31;
    const int warp_global = (blockIdx.x * blockDim.x + tid) >> 5;
    const int total_warps = (gridDim.x * blockDim.x) >> 5;
    const float4 z = make_float4(0.f, 0.f, 0.f, 0.f);

    // ---- Phase 0: classify + worklist + zero masked rows ----
    for (int base = warp_global * 32; base < n_ent; base += total_warps * 32) {
        int node = base + lane;
        bool valid  = (node < n_ent);
        bool active = valid && (__ldg(degrees + node) <= SPARSE_THRESHOLD);

        unsigned act_mask = __ballot_sync(0xffffffffu, active);
        int n_act = __popc(act_mask);
        int ofs = 0;
        if (lane == 0 && n_act)
            ofs = atomicAdd(&g_count, n_act);
        ofs = __shfl_sync(0xffffffffu, ofs, 0);
        if (active) {
            int rank = __popc(act_mask & ((1u << lane) - 1u));
            worklist[ofs + rank] = node;
        }

        unsigned msk = __ballot_sync(0xffffffffu, valid && !active);
        while (msk) {
            int j = __ffs(msk) - 1;
            msk &= msk - 1u;
            store_cs(out + (size_t)(base + j) * 32 + lane, z);
        }
    }

    // ---- Wait for prep's row_ptr (PDL dependency) ----
    cudaGridDependencySynchronize();

    // ---- Grid barrier: make all blocks' worklist writes visible ----
    __syncthreads();
    if (tid == 0) {
        __threadfence();
        atomicAdd(&g_bar, 1u);
        while (atomicAdd(&g_bar, 0u) < (unsigned)gridDim.x)
            __nanosleep(64);
        __threadfence();
    }
    __syncthreads();

    // ---- Phase 1: gather for active nodes ----
    const int n_active = g_count;
    for (int i = warp_global; i < n_active; i += total_warps) {
        const int node  = worklist[i];
        const int start = row_ptr[node];
        const int end   = row_ptr[node + 1];
        const int cnt   = end - start;

        float4 a0 = z, a1 = z;

        int e = start;
        for (; e + 8 <= end; e += 8) {
            int c0 = __ldg(cols + e);
            int c1 = __ldg(cols + e + 1);
            int c2 = __ldg(cols + e + 2);
            int c3 = __ldg(cols + e + 3);
            int c4 = __ldg(cols + e + 4);
            int c5 = __ldg(cols + e + 5);
            int c6 = __ldg(cols + e + 6);
            int c7 = __ldg(cols + e + 7);
            float4 v0 = __ldg(embeds + (size_t)c0 * 32 + lane);
            float4 v1 = __ldg(embeds + (size_t)c1 * 32 + lane);
            float4 v2 = __ldg(embeds + (size_t)c2 * 32 + lane);
            float4 v3 = __ldg(embeds + (size_t)c3 * 32 + lane);
            float4 v4 = __ldg(embeds + (size_t)c4 * 32 + lane);
            float4 v5 = __ldg(embeds + (size_t)c5 * 32 + lane);
            float4 v6 = __ldg(embeds + (size_t)c6 * 32 + lane);
            float4 v7 = __ldg(embeds + (size_t)c7 * 32 + lane);
            a0.x += (v0.x + v2.x) + (v4.x + v6.x);
            a0.y += (v0.y + v2.y) + (v4.y + v6.y);
            a0.z += (v0.z + v2.z) + (v4.z + v6.z);
            a0.w += (v0.w + v2.w) + (v4.w + v6.w);
            a1.x += (v1.x + v3.x) + (v5.x + v7.x);
            a1.y += (v1.y + v3.y) + (v5.y + v7.y);
            a1.z += (v1.z + v3.z) + (v5.z + v7.z);
            a1.w += (v1.w + v3.w) + (v5.w + v7.w);
        }
        for (; e < end; e++) {
            int c = __ldg(cols + e);
            float4 v = __ldg(embeds + (size_t)c * 32 + lane);
            a0.x += v.x; a0.y += v.y; a0.z += v.z; a0.w += v.w;
        }

        const float inv = 1.0f / (float)(cnt > 0 ? cnt : 1);
        float4 r;
        r.x = (a0.x + a1.x) * inv;
        r.y = (a0.y + a1.y) * inv;
        r.z = (a0.z + a1.z) * inv;
        r.w = (a0.w + a1.w) * inv;
        store_cs(out + (size_t)node * 32 + lane, r);
    }

    // ---- Tail: last-done block resets counters (all have passed barrier) --
    __syncthreads();
    if (tid == 0) {
        int d = atomicAdd(&g_done, 1);
        if (d == (int)gridDim.x - 1) {
            __threadfence();
            g_count = 0;
            g_bar   = 0u;
            g_done  = 0;
        }
    }
}

extern "C" void kernel_launch(void* const* d_in, const int* in_sizes, int n_in,
                              void* d_out, int out_size)
{
    const float4* embeds  = (const float4*)d_in[0];  // [N_ENT, 128] f32
    const int*    degrees = (const int*)d_in[1];     // [N_ENT] i32
    const int*    rows    = (const int*)d_in[2];     // [E] i32 (sorted)
    const int*    cols    = (const int*)d_in[3];     // [E] i32

    const int n_ent   = in_sizes[1];
    const int n_edges = in_sizes[2];
    float4* out = (float4*)d_out;

    int *row_ptr, *worklist;
    cudaGetSymbolAddress((void**)&row_ptr,  g_row_ptr);
    cudaGetSymbolAddress((void**)&worklist, g_worklist);

    const int edge_threads = n_edges / 8 + 1;
    prep_kernel<<<(edge_threads + 255) / 256, 256>>>(rows, row_ptr,
                                                     n_edges, n_ent);

    // Gather with Programmatic Dependent Launch: starts while prep runs,
    // overlaps phase 0 (degrees/out only), syncs before touching row_ptr.
    cudaLaunchConfig_t cfg = {};
    cfg.gridDim  = dim3(148 * 6, 1, 1);
    cfg.blockDim = dim3(256, 1, 1);
    cudaLaunchAttribute attr[1];
    attr[0].id = cudaLaunchAttributeProgrammaticStreamSerialization;
    attr[0].val.programmaticStreamSerializationAllowed = 1;
    cfg.attrs = attr;
    cfg.numAttrs = 1;

    cudaLaunchKernelEx(&cfg, gather_kernel,
                       embeds, degrees, (const int*)row_ptr, cols,
                       worklist, out, n_ent);
}

// round 14
// speedup vs baseline: 1.1671x; 1.1671x over previous
#include <cuda_runtime.h>

#define N_ENT_MAX 100000
#define SPARSE_THRESHOLD 5

// Scratch (graph-capturable, no allocs). Zero-initialized at module load;
// the gather kernel self-resets counters so every launch/replay starts clean.
__device__ int g_row_ptr[N_ENT_MAX + 1];
__device__ int g_worklist[N_ENT_MAX];
__device__ int g_count;
__device__ int g_done;

__device__ __forceinline__ void store_cs(float4* p, float4 v) {
    asm volatile("st.global.cs.v4.f32 [%0], {%1,%2,%3,%4};"
                 :: "l"(p), "f"(v.x), "f"(v.y), "f"(v.z), "f"(v.w) : "memory");
}

// ---------------------------------------------------------------------------
// Prep: (a) CSR row_ptr boundary-detect, 8 edges/thread via 2x int4
//       (b) worklist of active (deg<=5) nodes, warp-aggregated atomics
// Every block TRIGGERS the dependent gather launch at entry (PDL), so the
// gather's prep-independent phase 0 runs concurrently with this kernel.
// ---------------------------------------------------------------------------
__global__ void __launch_bounds__(256)
prep_kernel(const int* __restrict__ rows,
            const int* __restrict__ degrees,
            int* __restrict__ row_ptr,
            int* __restrict__ worklist,
            int n_edges, int n_ent, int edge_blocks)
{
    cudaTriggerProgrammaticLaunchCompletion();

    if (blockIdx.x < edge_blocks) {
        int t  = blockIdx.x * 256 + threadIdx.x;
        int e0 = t * 8;
        if (e0 > n_edges) return;

        int r[9];
        r[0] = (e0 > 0) ? rows[e0 - 1] : -1;
        if (e0 + 8 <= n_edges) {
            int4 v0 = *(const int4*)(rows + e0);
            int4 v1 = *(const int4*)(rows + e0 + 4);
            r[1] = v0.x; r[2] = v0.y; r[3] = v0.z; r[4] = v0.w;
            r[5] = v1.x; r[6] = v1.y; r[7] = v1.z; r[8] = v1.w;
        } else {
            #pragma unroll
            for (int k = 0; k < 8; k++)
                r[k + 1] = (e0 + k < n_edges) ? rows[e0 + k] : n_ent;
        }
        #pragma unroll
        for (int k = 0; k < 8; k++) {
            int e = e0 + k;
            if (e > n_edges) break;
            for (int node = r[k] + 1; node <= r[k + 1]; node++)
                row_ptr[node] = e;
        }
        return;
    }

    const int node = (blockIdx.x - edge_blocks) * 256 + threadIdx.x;
    const int lane = threadIdx.x & 31;
    bool active = (node < n_ent) && (degrees[node] <= SPARSE_THRESHOLD);

    unsigned act_mask = __ballot_sync(0xffffffffu, active);
    int n_act = __popc(act_mask);
    int ofs = 0;
    if (lane == 0 && n_act)
        ofs = atomicAdd(&g_count, n_act);
    ofs = __shfl_sync(0xffffffffu, ofs, 0);
    if (active) {
        int rank = __popc(act_mask & ((1u << lane) - 1u));
        worklist[ofs + rank] = node;
    }
}

// ---------------------------------------------------------------------------
// Gather (persistent, one wave = 148*6 blocks), launched with PDL:
//  Phase 0: zero-fill masked rows — depends ONLY on degrees/out, runs
//           CONCURRENTLY with prep (prep triggers at block entry).
//  Sync   : cudaGridDependencySynchronize() — prep grid complete + visible.
//  Phase 1: one warp per active node from the worklist; unroll-8 gathers.
//  Tail   : last block resets g_count/g_done so the next replay starts clean.
// ---------------------------------------------------------------------------
__global__ void __launch_bounds__(256, 6)
gather_kernel(const float4* __restrict__ embeds,
              const int* __restrict__ degrees,
              const int* __restrict__ row_ptr,
              const int* __restrict__ cols,
              const int* __restrict__ worklist,
              float4* __restrict__ out,
              int n_ent)
{
    const int lane = threadIdx.x & 31;
    const int warp_global = (blockIdx.x * blockDim.x + threadIdx.x) >> 5;
    const int total_warps = (gridDim.x * blockDim.x) >> 5;
    const float4 z = make_float4(0.f, 0.f, 0.f, 0.f);

    // ---- Phase 0: zero masked rows (overlaps the prep kernel) ----
    for (int base = warp_global * 32; base < n_ent; base += total_warps * 32) {
        int node = base + lane;
        bool masked = (node < n_ent) && (__ldg(degrees + node) > SPARSE_THRESHOLD);
        unsigned m = __ballot_sync(0xffffffffu, masked);
        while (m) {
            int j = __ffs(m) - 1;
            m &= m - 1u;
            store_cs(out + (size_t)(base + j) * 32 + lane, z);
        }
    }

    // ---- Wait for prep's grid to complete (PDL dependency) ----
    cudaGridDependencySynchronize();

    // ---- Phase 1: gather for active nodes ----
    const int n_active = g_count;
    for (int i = warp_global; i < n_active; i += total_warps) {
        const int node  = worklist[i];
        const int start = row_ptr[node];
        const int end   = row_ptr[node + 1];
        const int cnt   = end - start;

        float4 a0 = z, a1 = z;

        int e = start;
        for (; e + 8 <= end; e += 8) {
            int c0 = __ldg(cols + e);
            int c1 = __ldg(cols + e + 1);
            int c2 = __ldg(cols + e + 2);
            int c3 = __ldg(cols + e + 3);
            int c4 = __ldg(cols + e + 4);
            int c5 = __ldg(cols + e + 5);
            int c6 = __ldg(cols + e + 6);
            int c7 = __ldg(cols + e + 7);
            float4 v0 = __ldg(embeds + (size_t)c0 * 32 + lane);
            float4 v1 = __ldg(embeds + (size_t)c1 * 32 + lane);
            float4 v2 = __ldg(embeds + (size_t)c2 * 32 + lane);
            float4 v3 = __ldg(embeds + (size_t)c3 * 32 + lane);
            float4 v4 = __ldg(embeds + (size_t)c4 * 32 + lane);
            float4 v5 = __ldg(embeds + (size_t)c5 * 32 + lane);
            float4 v6 = __ldg(embeds + (size_t)c6 * 32 + lane);
            float4 v7 = __ldg(embeds + (size_t)c7 * 32 + lane);
            a0.x += (v0.x + v2.x) + (v4.x + v6.x);
            a0.y += (v0.y + v2.y) + (v4.y + v6.y);
            a0.z += (v0.z + v2.z) + (v4.z + v6.z);
            a0.w += (v0.w + v2.w) + (v4.w + v6.w);
            a1.x += (v1.x + v3.x) + (v5.x + v7.x);
            a1.y += (v1.y + v3.y) + (v5.y + v7.y);
            a1.z += (v1.z + v3.z) + (v5.z + v7.z);
            a1.w += (v1.w + v3.w) + (v5.w + v7.w);
        }
        for (; e < end; e++) {
            int c = __ldg(cols + e);
            float4 v = __ldg(embeds + (size_t)c * 32 + lane);
            a0.x += v.x; a0.y += v.y; a0.z += v.z; a0.w += v.w;
        }

        const float inv = 1.0f / (float)(cnt > 0 ? cnt : 1);
        float4 r;
        r.x = (a0.x + a1.x) * inv;
        r.y = (a0.y + a1.y) * inv;
        r.z = (a0.z + a1.z) * inv;
        r.w = (a0.w + a1.w) * inv;
        store_cs(out + (size_t)node * 32 + lane, r);
    }

    // ---- Tail: last block resets counters for the next launch/replay ----
    __syncthreads();
    if (threadIdx.x == 0) {
        int d = atomicAdd(&g_done, 1);
        if (d == (int)gridDim.x - 1) {
            g_count = 0;
            g_done  = 0;
        }
    }
}

extern "C" void kernel_launch(void* const* d_in, const int* in_sizes, int n_in,
                              void* d_out, int out_size)
{
    const float4* embeds  = (const float4*)d_in[0];  // [N_ENT, 128] f32
    const int*    degrees = (const int*)d_in[1];     // [N_ENT] i32
    const int*    rows    = (const int*)d_in[2];     // [E] i32 (sorted)
    const int*    cols    = (const int*)d_in[3];     // [E] i32

    const int n_ent   = in_sizes[1];
    const int n_edges = in_sizes[2];
    float4* out = (float4*)d_out;

    int *row_ptr, *worklist;
    cudaGetSymbolAddress((void**)&row_ptr,  g_row_ptr);
    cudaGetSymbolAddress((void**)&worklist, g_worklist);

    const int edge_threads = n_edges / 8 + 1;
    const int edge_blocks  = (edge_threads + 255) / 256;
    const int node_blocks  = (n_ent + 255) / 256;
    prep_kernel<<<edge_blocks + node_blocks, 256>>>(
        rows, degrees, row_ptr, worklist, n_edges, n_ent, edge_blocks);

    // Gather launched with Programmatic Dependent Launch: prep triggers at
    // block entry, so this grid launches immediately and overlaps phase 0
    // with prep; cudaGridDependencySynchronize() gates phase 1.
    cudaLaunchConfig_t cfg = {};
    cfg.gridDim  = dim3(148 * 6, 1, 1);
    cfg.blockDim = dim3(256, 1, 1);
    cudaLaunchAttribute attr[1];
    attr[0].id = cudaLaunchAttributeProgrammaticStreamSerialization;
    attr[0].val.programmaticStreamSerializationAllowed = 1;
    cfg.attrs = attr;
    cfg.numAttrs = 1;

    cudaLaunchKernelEx(&cfg, gather_kernel,
                       embeds, degrees, (const int*)row_ptr, cols,
                       (const int*)worklist, out, n_ent);
}